// round 6
// baseline (speedup 1.0000x reference)
#include <cuda_runtime.h>
#include <cuda_fp16.h>
#include <cuda_bf16.h>
#include <cstdint>

#define BATCH      32
#define W_DIM      512
#define CHANNELS   1024
#define GRID_HW    64
#define HW         (GRID_HW * GRID_HW)      // 4096
#define TWO_PI     6.28318530717958647692f
#define GAIN       0.044194173824159216f    // 1/sqrt(512)
#define WSCALE     0.03125f                 // 1/sqrt(1024)

// ---------------- scratch (device globals; no runtime alloc) -----------------
__device__ float  g_frx[BATCH * CHANNELS];
__device__ float  g_fry[BATCH * CHANNELS];
__device__ float  g_ph [BATCH * CHANNELS];
__device__ float  g_amp[BATCH * CHANNELS];

// fp16 trig tables, p (w or h) FASTEST: [b][c][p]
__device__ __half g_SAt[BATCH * CHANNELS * GRID_HW];
__device__ __half g_CAt[BATCH * CHANNELS * GRID_HW];
__device__ __half g_SBt[BATCH * CHANNELS * GRID_HW];
__device__ __half g_CBt[BATCH * CHANNELS * GRID_HW];

// fp16 weight (1/sqrt(C) folded), row-major [o][c]
__device__ __half g_Wh[CHANNELS * CHANNELS];

// ---------------- PTX helpers -----------------------------------------------
__device__ __forceinline__ uint32_t smem_u32(const void* p) {
    uint32_t a;
    asm("{ .reg .u64 t; cvta.to.shared.u64 t, %1; cvt.u32.u64 %0, t; }"
        : "=r"(a) : "l"(p));
    return a;
}

__device__ __forceinline__ void ldsm4(uint32_t* r, uint32_t addr) {
    asm volatile("ldmatrix.sync.aligned.m8n8.x4.shared.b16 {%0,%1,%2,%3}, [%4];"
                 : "=r"(r[0]), "=r"(r[1]), "=r"(r[2]), "=r"(r[3]) : "r"(addr));
}
__device__ __forceinline__ void ldsm4t(uint32_t* r, uint32_t addr) {
    asm volatile("ldmatrix.sync.aligned.m8n8.x4.trans.shared.b16 {%0,%1,%2,%3}, [%4];"
                 : "=r"(r[0]), "=r"(r[1]), "=r"(r[2]), "=r"(r[3]) : "r"(addr));
}

__device__ __forceinline__ void mma16816(float* d, const uint32_t* a,
                                         const uint32_t* b) {
    asm volatile(
        "mma.sync.aligned.m16n8k16.row.col.f32.f16.f16.f32 "
        "{%0,%1,%2,%3}, {%4,%5,%6,%7}, {%8,%9}, {%0,%1,%2,%3};"
        : "+f"(d[0]), "+f"(d[1]), "+f"(d[2]), "+f"(d[3])
        : "r"(a[0]), "r"(a[1]), "r"(a[2]), "r"(a[3]), "r"(b[0]), "r"(b[1]));
}

__device__ __forceinline__ void cp16(uint32_t dst, const void* src) {
    asm volatile("cp.async.ca.shared.global [%0], [%1], 16;"
                 :: "r"(dst), "l"(src));
}
__device__ __forceinline__ void cp4(uint32_t dst, const void* src) {
    asm volatile("cp.async.ca.shared.global [%0], [%1], 4;"
                 :: "r"(dst), "l"(src));
}
#define CP_COMMIT() asm volatile("cp.async.commit_group;" ::: "memory")
#define CP_WAIT0()  asm volatile("cp.async.wait_group 0;"  ::: "memory")
#define CP_WAIT1()  asm volatile("cp.async.wait_group 1;"  ::: "memory")

// ---------------- stage 1: per-batch params ----------------------------------
__global__ void params_kernel(const float* __restrict__ w,
                              const float* __restrict__ affine_w,
                              const float* __restrict__ affine_b,
                              const float* __restrict__ freqs,
                              const float* __restrict__ phases) {
    __shared__ float t[BATCH][4];
    __shared__ float cs[BATCH], ss[BATCH], trx[BATCH], trY[BATCH];

    int tid = threadIdx.x;          // 128 threads
    int b = tid >> 2, j = tid & 3;

    float acc = 0.f;
    const float* wr = w + b * W_DIM;
    const float* ar = affine_w + j * W_DIM;
    #pragma unroll 4
    for (int k = 0; k < W_DIM; k++) acc += wr[k] * ar[k];
    t[b][j] = acc * GAIN + affine_b[j];
    __syncthreads();

    if (j == 0) {
        float t0 = t[b][0], t1 = t[b][1], t2 = t[b][2], t3 = t[b][3];
        float inv = rsqrtf(t0 * t0 + t1 * t1);
        float c = t0 * inv, s = t1 * inv, tx = t2 * inv, ty = t3 * inv;
        cs[b] = c; ss[b] = s;
        trx[b] = -c * tx + s * ty;
        trY[b] = -s * tx - c * ty;
    }
    __syncthreads();

    for (int idx = tid; idx < BATCH * CHANNELS; idx += 128) {
        int bb = idx >> 10, c = idx & (CHANNELS - 1);
        float f0 = freqs[c * 2], f1 = freqs[c * 2 + 1];
        float C = cs[bb], S = ss[bb];
        float frx = f0 * C + f1 * S;
        float fry = -f0 * S + f1 * C;
        float ph  = phases[c] + f0 * trx[bb] + f1 * trY[bb];
        float nrm = sqrtf(frx * frx + fry * fry);
        float amp = 1.0f - (nrm - 2.0f) * (1.0f / 30.0f);
        amp = fminf(fmaxf(amp, 0.0f), 1.0f);
        g_frx[idx] = frx; g_fry[idx] = fry; g_ph[idx] = ph; g_amp[idx] = amp;
    }
}

// ---------------- stage 1b: weight -> fp16 -----------------------------------
__global__ void wconv_kernel(const float* __restrict__ weight) {
    int idx = blockIdx.x * blockDim.x + threadIdx.x;
    for (int i = idx; i < CHANNELS * CHANNELS; i += gridDim.x * blockDim.x)
        g_Wh[i] = __float2half(weight[i] * WSCALE);
}

// ---------------- stage 2: fp16 trig tables (p-fastest) ----------------------
__global__ void tables_kernel() {
    int tid = threadIdx.x;                       // 256
    int c = blockIdx.x * 4 + (tid >> 6);
    int p = tid & 63;
    int b = blockIdx.y;
    int pi = b * CHANNELS + c;
    float g = ((2 * p + 1) * (1.0f / GRID_HW) - 1.0f) * 0.5f;
    float frx = g_frx[pi], fry = g_fry[pi];
    float ph = g_ph[pi], amp = g_amp[pi];
    float sa, ca, sb, cb;
    sincosf(TWO_PI * g * frx, &sa, &ca);
    sincosf(TWO_PI * (g * fry + ph), &sb, &cb);
    int o = pi * GRID_HW + p;
    g_SAt[o] = __float2half(amp * sa);
    g_CAt[o] = __float2half(amp * ca);
    g_SBt[o] = __float2half(sb);
    g_CBt[o] = __float2half(cb);
}

// ---------------- stage 3: fused mma.sync GEMM -------------------------------
// CTA tile: M=128 (o) x N=128 (px), K=1024 in 32 iters of BK=32.
// 8 warps, 32x64 warp tiles (4m x 2n), 2 CTAs/SM for latency hiding.
#define BK       32
#define NKIT     (CHANNELS / BK)
#define ASTRIDE  40      // halves
#define BSTRIDE  136     // halves
#define TSTRIDE  72      // halves

#define ABUF     5120    // halves per A buffer (128*40)
#define BBUF     4352    // halves per B buffer (32*136)
#define T_CA     2304
#define T_SB     4608
#define T_CB     4672
#define TBUF     4736    // halves per table buffer

#define OFF_A    0                          // 3 * 5120 = 15360
#define OFF_B    15360                      // 2 * 4352 = 8704
#define OFF_T    24064                      // 3 * 4736 = 14208
#define SMEM_HALVES (24064 + 3 * 4736)      // 38272
#define SMEM_BYTES  (SMEM_HALVES * 2)       // 76544

__global__ void __launch_bounds__(256, 2)
gemm_mma(float* __restrict__ out) {
    extern __shared__ __half sh[];
    int tid = threadIdx.x;
    int ot = blockIdx.x;   // 8
    int pt = blockIdx.y;   // 32
    int b  = blockIdx.z;   // 32

    uint32_t sAu = smem_u32(sh + OFF_A);
    uint32_t sBu = smem_u32(sh + OFF_B);
    uint32_t sTu = smem_u32(sh + OFF_T);
    int h0 = pt * 2;

    // ---- staging maps -------------------------------------------------------
    int arow = tid >> 2, aseg = tid & 3;                 // A: 4 lanes/row, 64 rows/pass
    const __half* wsrc0 = g_Wh + (size_t)(ot * 128 + arow) * CHANNELS + aseg * 8;
    int trow = tid >> 3, tseg = tid & 7;                 // tables: 8 lanes/row

    auto stage_A = [&](int k, int buf3) {
        uint32_t ad = sAu + (uint32_t)(buf3 * ABUF + arow * ASTRIDE + aseg * 8) * 2;
        const __half* ws = wsrc0 + k * BK;
        #pragma unroll
        for (int j = 0; j < 2; j++)
            cp16(ad + (uint32_t)(j * 64 * ASTRIDE) * 2, ws + (size_t)j * 64 * CHANNELS);
    };
    auto stage_T = [&](int k, int buf3) {
        int ck = k * BK;
        const __half* sasrc = g_SAt + ((size_t)(b * CHANNELS + ck + trow) << 6) + tseg * 8;
        const __half* casrc = g_CAt + ((size_t)(b * CHANNELS + ck + trow) << 6) + tseg * 8;
        uint32_t td = sTu + (uint32_t)(buf3 * TBUF + trow * TSTRIDE + tseg * 8) * 2;
        cp16(td, sasrc);
        cp16(td + T_CA * 2, casrc);
        if (tid < 32) {
            const __half* s = g_SBt + ((size_t)(b * CHANNELS + ck + tid) << 6) + h0;
            cp4(sTu + (uint32_t)(buf3 * TBUF + T_SB + tid * 2) * 2, s);
        } else if (tid < 64) {
            int c = tid - 32;
            const __half* s = g_CBt + ((size_t)(b * CHANNELS + ck + c) << 6) + h0;
            cp4(sTu + (uint32_t)(buf3 * TBUF + T_CB + c * 2) * 2, s);
        }
    };

    // ---- genB map -----------------------------------------------------------
    int gc = tid >> 3;            // c row 0..31
    int gj = tid & 7;             // px-16 group
    int gpx = gj * 16;
    int gh = gpx >> 6;            // 0..1
    int gw = gpx & 63;

    auto genB = [&](int tbuf, int bbuf) {
        const __half* T = sh + OFF_T + tbuf * TBUF;
        __half2 sb2 = __half2half2(T[T_SB + gc * 2 + gh]);
        __half2 cb2 = __half2half2(T[T_CB + gc * 2 + gh]);
        __half* d = sh + OFF_B + bbuf * BBUF + gc * BSTRIDE + gpx;
        #pragma unroll
        for (int half8 = 0; half8 < 2; half8++) {
            uint4 xsa = *(const uint4*)(T + gc * TSTRIDE + gw + half8 * 8);
            uint4 xca = *(const uint4*)(T + T_CA + gc * TSTRIDE + gw + half8 * 8);
            uint4 o0;
            #pragma unroll
            for (int j = 0; j < 4; j++)
                ((__half2*)&o0)[j] = __hfma2(((const __half2*)&xsa)[j], cb2,
                                     __hmul2(((const __half2*)&xca)[j], sb2));
            *(uint4*)(d + half8 * 8) = o0;
        }
    };

    // ---- mma geometry -------------------------------------------------------
    int wid = tid >> 5, lane = tid & 31;
    int m0 = (wid & 3) * 32;      // 0..96
    int n0 = (wid >> 2) * 64;     // 0 / 64
    uint32_t aAddr0 = sAu + (uint32_t)((m0 + (lane & 15)) * ASTRIDE + (lane >> 4) * 8) * 2;
    uint32_t bAddr0 = sBu + (uint32_t)((lane & 15) * BSTRIDE + n0 + (lane >> 4) * 8) * 2;

    float acc[2][8][4];
    #pragma unroll
    for (int i = 0; i < 2; i++)
        #pragma unroll
        for (int j = 0; j < 8; j++)
            #pragma unroll
            for (int q = 0; q < 4; q++) acc[i][j][q] = 0.f;

    // ---- prologue: stage T0, T1, A0; genB(0) --------------------------------
    stage_A(0, 0);
    stage_T(0, 0);
    stage_T(1, 1);
    CP_COMMIT();
    CP_WAIT0();
    __syncthreads();
    genB(0, 0);

    // ---- main loop: 1 barrier per iter --------------------------------------
    int a_cur = 0, t_nxt = 1, b_cur = 0;
    #pragma unroll 1
    for (int k = 0; k < NKIT; k++) {
        int a_nxt = a_cur + 1; if (a_nxt == 3) a_nxt = 0;
        int t_n2  = t_nxt + 1; if (t_n2 == 3) t_n2 = 0;

        // stage ahead: A(k+1), T(k+2)
        if (k + 1 < NKIT) stage_A(k + 1, a_nxt);
        if (k + 2 < NKIT) stage_T(k + 2, t_n2);
        CP_COMMIT();
        CP_WAIT1();            // group from iter k-1 (A(k), T(k+1)) complete
        __syncthreads();       // genB(k) visible; buffers safe

        // -- MMA(k) -----------------------------------------------------------
        uint32_t aA = aAddr0 + (uint32_t)(a_cur * ABUF) * 2;
        uint32_t bA = bAddr0 + (uint32_t)(b_cur * BBUF) * 2;
        #pragma unroll
        for (int ks = 0; ks < 2; ks++) {
            uint32_t af[2][4], bf[4][4];
            #pragma unroll
            for (int im = 0; im < 2; im++)
                ldsm4(af[im], aA + (uint32_t)(im * 16 * ASTRIDE) * 2 + ks * 32);
            #pragma unroll
            for (int in = 0; in < 4; in++)
                ldsm4t(bf[in], bA + (uint32_t)(ks * 16 * BSTRIDE) * 2 + in * 32);
            #pragma unroll
            for (int im = 0; im < 2; im++)
                #pragma unroll
                for (int in = 0; in < 4; in++) {
                    mma16816(acc[im][2 * in],     af[im], &bf[in][0]);
                    mma16816(acc[im][2 * in + 1], af[im], &bf[in][2]);
                }
        }

        // -- genB(k+1) (other CTA on the SM overlaps this with its MMA) -------
        if (k + 1 < NKIT) genB(t_nxt, b_cur ^ 1);

        a_cur = a_nxt;
        t_nxt = t_n2;
        b_cur ^= 1;
    }

    // ---- epilogue: direct STG, 32B-sector coalesced -------------------------
    #pragma unroll
    for (int im = 0; im < 2; im++) {
        int o = ot * 128 + m0 + im * 16 + (lane >> 2);
        float* p = out + ((size_t)(b * CHANNELS + o)) * HW
                       + (size_t)pt * 128 + n0 + 2 * (lane & 3);
        #pragma unroll
        for (int inf = 0; inf < 8; inf++) {
            float2 vlo = make_float2(acc[im][inf][0], acc[im][inf][1]);
            float2 vhi = make_float2(acc[im][inf][2], acc[im][inf][3]);
            *(float2*)(p + inf * 8)          = vlo;   // row o
            *(float2*)(p + inf * 8 + 8 * HW) = vhi;   // row o+8
        }
    }
}

// ---------------- launch ------------------------------------------------------
extern "C" void kernel_launch(void* const* d_in, const int* in_sizes, int n_in,
                              void* d_out, int out_size) {
    const float* w        = (const float*)d_in[0];
    const float* affine_w = (const float*)d_in[1];
    const float* affine_b = (const float*)d_in[2];
    const float* freqs    = (const float*)d_in[3];
    const float* phases   = (const float*)d_in[4];
    const float* weight   = (const float*)d_in[5];
    float* out = (float*)d_out;

    cudaFuncSetAttribute(gemm_mma, cudaFuncAttributeMaxDynamicSharedMemorySize,
                         SMEM_BYTES);

    params_kernel<<<1, 128>>>(w, affine_w, affine_b, freqs, phases);
    wconv_kernel<<<512, 256>>>(weight);
    tables_kernel<<<dim3(CHANNELS / 4, BATCH), 256>>>();
    gemm_mma<<<dim3(8, 32, BATCH), 256, SMEM_BYTES>>>(out);
}

// round 7
// speedup vs baseline: 1.1367x; 1.1367x over previous
#include <cuda_runtime.h>
#include <cuda_fp16.h>
#include <cuda_bf16.h>
#include <cstdint>

#define BATCH      32
#define W_DIM      512
#define CHANNELS   1024
#define GRID_HW    64
#define HW         (GRID_HW * GRID_HW)      // 4096
#define TWO_PI     6.28318530717958647692f
#define GAIN       0.044194173824159216f    // 1/sqrt(512)
#define WSCALE     0.03125f                 // 1/sqrt(1024)

// ---------------- scratch (device globals; no runtime alloc) -----------------
__device__ float  g_frx[BATCH * CHANNELS];
__device__ float  g_fry[BATCH * CHANNELS];
__device__ float  g_ph [BATCH * CHANNELS];
__device__ float  g_amp[BATCH * CHANNELS];

// fp16 trig tables, p (w or h) FASTEST: [b][c][p]
__device__ __half g_SAt[BATCH * CHANNELS * GRID_HW];
__device__ __half g_CAt[BATCH * CHANNELS * GRID_HW];
__device__ __half g_SBt[BATCH * CHANNELS * GRID_HW];
__device__ __half g_CBt[BATCH * CHANNELS * GRID_HW];

// fp16 weight (1/sqrt(C) folded), row-major [o][c]
__device__ __half g_Wh[CHANNELS * CHANNELS];

// ---------------- PTX helpers -----------------------------------------------
__device__ __forceinline__ uint32_t smem_u32(const void* p) {
    uint32_t a;
    asm("{ .reg .u64 t; cvta.to.shared.u64 t, %1; cvt.u32.u64 %0, t; }"
        : "=r"(a) : "l"(p));
    return a;
}

__device__ __forceinline__ void ldsm4(uint32_t* r, uint32_t addr) {
    asm volatile("ldmatrix.sync.aligned.m8n8.x4.shared.b16 {%0,%1,%2,%3}, [%4];"
                 : "=r"(r[0]), "=r"(r[1]), "=r"(r[2]), "=r"(r[3]) : "r"(addr));
}
__device__ __forceinline__ void ldsm4t(uint32_t* r, uint32_t addr) {
    asm volatile("ldmatrix.sync.aligned.m8n8.x4.trans.shared.b16 {%0,%1,%2,%3}, [%4];"
                 : "=r"(r[0]), "=r"(r[1]), "=r"(r[2]), "=r"(r[3]) : "r"(addr));
}

__device__ __forceinline__ void mma16816(float* d, const uint32_t* a,
                                         const uint32_t* b) {
    asm volatile(
        "mma.sync.aligned.m16n8k16.row.col.f32.f16.f16.f32 "
        "{%0,%1,%2,%3}, {%4,%5,%6,%7}, {%8,%9}, {%0,%1,%2,%3};"
        : "+f"(d[0]), "+f"(d[1]), "+f"(d[2]), "+f"(d[3])
        : "r"(a[0]), "r"(a[1]), "r"(a[2]), "r"(a[3]), "r"(b[0]), "r"(b[1]));
}

__device__ __forceinline__ void cp16(uint32_t dst, const void* src) {
    asm volatile("cp.async.ca.shared.global [%0], [%1], 16;"
                 :: "r"(dst), "l"(src));
}
__device__ __forceinline__ void cp4(uint32_t dst, const void* src) {
    asm volatile("cp.async.ca.shared.global [%0], [%1], 4;"
                 :: "r"(dst), "l"(src));
}
#define CP_COMMIT() asm volatile("cp.async.commit_group;" ::: "memory")
#define CP_WAIT0()  asm volatile("cp.async.wait_group 0;"  ::: "memory")
#define CP_WAIT2()  asm volatile("cp.async.wait_group 2;"  ::: "memory")

// ---------------- stage 1: per-batch params ----------------------------------
__global__ void params_kernel(const float* __restrict__ w,
                              const float* __restrict__ affine_w,
                              const float* __restrict__ affine_b,
                              const float* __restrict__ freqs,
                              const float* __restrict__ phases) {
    __shared__ float t[BATCH][4];
    __shared__ float cs[BATCH], ss[BATCH], trx[BATCH], trY[BATCH];

    int tid = threadIdx.x;          // 128 threads
    int b = tid >> 2, j = tid & 3;

    float acc = 0.f;
    const float* wr = w + b * W_DIM;
    const float* ar = affine_w + j * W_DIM;
    #pragma unroll 4
    for (int k = 0; k < W_DIM; k++) acc += wr[k] * ar[k];
    t[b][j] = acc * GAIN + affine_b[j];
    __syncthreads();

    if (j == 0) {
        float t0 = t[b][0], t1 = t[b][1], t2 = t[b][2], t3 = t[b][3];
        float inv = rsqrtf(t0 * t0 + t1 * t1);
        float c = t0 * inv, s = t1 * inv, tx = t2 * inv, ty = t3 * inv;
        cs[b] = c; ss[b] = s;
        trx[b] = -c * tx + s * ty;
        trY[b] = -s * tx - c * ty;
    }
    __syncthreads();

    for (int idx = tid; idx < BATCH * CHANNELS; idx += 128) {
        int bb = idx >> 10, c = idx & (CHANNELS - 1);
        float f0 = freqs[c * 2], f1 = freqs[c * 2 + 1];
        float C = cs[bb], S = ss[bb];
        float frx = f0 * C + f1 * S;
        float fry = -f0 * S + f1 * C;
        float ph  = phases[c] + f0 * trx[bb] + f1 * trY[bb];
        float nrm = sqrtf(frx * frx + fry * fry);
        float amp = 1.0f - (nrm - 2.0f) * (1.0f / 30.0f);
        amp = fminf(fmaxf(amp, 0.0f), 1.0f);
        g_frx[idx] = frx; g_fry[idx] = fry; g_ph[idx] = ph; g_amp[idx] = amp;
    }
}

// ---------------- stage 1b: weight -> fp16 -----------------------------------
__global__ void wconv_kernel(const float* __restrict__ weight) {
    int idx = blockIdx.x * blockDim.x + threadIdx.x;
    for (int i = idx; i < CHANNELS * CHANNELS; i += gridDim.x * blockDim.x)
        g_Wh[i] = __float2half(weight[i] * WSCALE);
}

// ---------------- stage 2: fp16 trig tables (p-fastest) ----------------------
__global__ void tables_kernel() {
    int tid = threadIdx.x;                       // 256
    int c = blockIdx.x * 4 + (tid >> 6);
    int p = tid & 63;
    int b = blockIdx.y;
    int pi = b * CHANNELS + c;
    float g = ((2 * p + 1) * (1.0f / GRID_HW) - 1.0f) * 0.5f;
    float frx = g_frx[pi], fry = g_fry[pi];
    float ph = g_ph[pi], amp = g_amp[pi];
    float sa, ca, sb, cb;
    sincosf(TWO_PI * g * frx, &sa, &ca);
    sincosf(TWO_PI * (g * fry + ph), &sb, &cb);
    int o = pi * GRID_HW + p;
    g_SAt[o] = __float2half(amp * sa);
    g_CAt[o] = __float2half(amp * ca);
    g_SBt[o] = __float2half(sb);
    g_CBt[o] = __float2half(cb);
}

// ---------------- stage 3: fused mma.sync GEMM -------------------------------
// CTA tile: M=256 (o) x N=128 (px), K=1024 in 16 iters of BK=64.
// 8 warps, 64x64 warp tiles (4m x 2n). genB interleaved at ks granularity.
#define BK       64
#define NKIT     (CHANNELS / BK)   // 16
#define ASTRIDE  72      // halves (64 + 8 pad)
#define BSTRIDE  136     // halves (128 + 8 pad)
#define TSTRIDE  72      // halves (64 + 8 pad)

#define ABUF     18432   // halves per A buffer (256*72)
#define BBUF     8704    // halves per B buffer (64*136)
#define T_CA     4608    // 64*72
#define T_SB     9216
#define T_CB     9344
#define TBUF     9472    // halves per table buffer

#define OFF_A    0                          // 3 * 18432 = 55296
#define OFF_B    55296                      // 2 * 8704  = 17408
#define OFF_T    72704                      // 3 * 9472  = 28416
#define SMEM_HALVES (72704 + 3 * 9472)      // 101120
#define SMEM_BYTES  (SMEM_HALVES * 2)       // 202240

__global__ void __launch_bounds__(256, 1)
gemm_mma(float* __restrict__ out) {
    extern __shared__ __half sh[];
    int tid = threadIdx.x;
    int ot = blockIdx.x;   // 4
    int pt = blockIdx.y;   // 32
    int b  = blockIdx.z;   // 32

    uint32_t sAu = smem_u32(sh + OFF_A);
    uint32_t sBu = smem_u32(sh + OFF_B);
    int h0 = pt * 2;

    // ---- staging maps -------------------------------------------------------
    int arow = tid >> 3, aseg = tid & 7;                 // A: 8 lanes/row, 32 rows/pass
    const __half* wsrc0 = g_Wh + (size_t)(ot * 256 + arow) * CHANNELS + aseg * 8;
    int trow = tid >> 3, tseg = tid & 7;                 // tables: 8 lanes/row

    auto stage_A = [&](int k, int buf3) {
        uint32_t ad = sAu + (uint32_t)(buf3 * ABUF + arow * ASTRIDE + aseg * 8) * 2;
        const __half* ws = wsrc0 + k * BK;
        #pragma unroll
        for (int j = 0; j < 8; j++)
            cp16(ad + (uint32_t)(j * 32 * ASTRIDE) * 2, ws + (size_t)j * 32 * CHANNELS);
    };
    auto stage_T = [&](int k, int buf3) {
        int ck = k * BK;
        uint32_t tb = smem_u32(sh + OFF_T) + (uint32_t)(buf3 * TBUF) * 2;
        #pragma unroll
        for (int j = 0; j < 2; j++) {
            int r = trow + j * 32;
            const __half* sasrc = g_SAt + ((size_t)(b * CHANNELS + ck + r) << 6) + tseg * 8;
            const __half* casrc = g_CAt + ((size_t)(b * CHANNELS + ck + r) << 6) + tseg * 8;
            uint32_t td = tb + (uint32_t)(r * TSTRIDE + tseg * 8) * 2;
            cp16(td, sasrc);
            cp16(td + T_CA * 2, casrc);
        }
        if (tid < 64) {
            const __half* s = g_SBt + ((size_t)(b * CHANNELS + ck + tid) << 6) + h0;
            cp4(tb + (uint32_t)(T_SB + tid * 2) * 2, s);
        } else if (tid < 128) {
            int c = tid - 64;
            const __half* s = g_CBt + ((size_t)(b * CHANNELS + ck + c) << 6) + h0;
            cp4(tb + (uint32_t)(T_CB + c * 2) * 2, s);
        }
    };

    // ---- genB map: thread -> (c rows {gc, gc+32}, 16-px group) --------------
    int gc = tid >> 3;            // 0..31
    int gj = tid & 7;
    int gpx = gj * 16;
    int gh = gpx >> 6;            // 0..1
    int gw = gpx & 63;

    struct GenRegs { uint4 xsa0, xsa1, xca0, xca1; __half2 sb2, cb2; };

    auto gen_load = [&](int crow, int tbuf, GenRegs& g) {
        const __half* T = sh + OFF_T + tbuf * TBUF;
        g.xsa0 = *(const uint4*)(T + crow * TSTRIDE + gw);
        g.xsa1 = *(const uint4*)(T + crow * TSTRIDE + gw + 8);
        g.xca0 = *(const uint4*)(T + T_CA + crow * TSTRIDE + gw);
        g.xca1 = *(const uint4*)(T + T_CA + crow * TSTRIDE + gw + 8);
        g.sb2 = __half2half2(T[T_SB + crow * 2 + gh]);
        g.cb2 = __half2half2(T[T_CB + crow * 2 + gh]);
    };
    auto gen_store = [&](int crow, int bbuf, const GenRegs& g) {
        uint4 o0, o1;
        #pragma unroll
        for (int j = 0; j < 4; j++) {
            ((__half2*)&o0)[j] = __hfma2(((const __half2*)&g.xsa0)[j], g.cb2,
                                 __hmul2(((const __half2*)&g.xca0)[j], g.sb2));
            ((__half2*)&o1)[j] = __hfma2(((const __half2*)&g.xsa1)[j], g.cb2,
                                 __hmul2(((const __half2*)&g.xca1)[j], g.sb2));
        }
        __half* d = sh + OFF_B + bbuf * BBUF + crow * BSTRIDE + gpx;
        *(uint4*)d = o0;
        *(uint4*)(d + 8) = o1;
    };

    // ---- mma geometry -------------------------------------------------------
    int wid = tid >> 5, lane = tid & 31;
    int m0 = (wid >> 1) * 64;     // 0..192
    int n0 = (wid & 1) * 64;      // 0 / 64
    uint32_t aAddr0 = sAu + (uint32_t)((m0 + (lane & 15)) * ASTRIDE + (lane >> 4) * 8) * 2;
    uint32_t bAddr0 = sBu + (uint32_t)((lane & 15) * BSTRIDE + n0 + (lane >> 4) * 8) * 2;

    float acc[4][8][4];
    #pragma unroll
    for (int i = 0; i < 4; i++)
        #pragma unroll
        for (int j = 0; j < 8; j++)
            #pragma unroll
            for (int q = 0; q < 4; q++) acc[i][j][q] = 0.f;

    // ---- prologue: A0, T0, T1; genB(0) --------------------------------------
    stage_A(0, 0); CP_COMMIT();
    stage_T(0, 0); CP_COMMIT();
    stage_T(1, 1); CP_COMMIT();
    CP_WAIT0();
    __syncthreads();
    {
        GenRegs g;
        gen_load(gc, 0, g);      gen_store(gc, 0, g);
        gen_load(gc + 32, 0, g); gen_store(gc + 32, 0, g);
    }

    // ---- main loop ----------------------------------------------------------
    // invariants at iter k: A(k) in buf k%3, B(k) in buf k&1 (built last iter),
    // T(k+1) in buf (k+1)%3 ready after wait; stage A(k+1), T(k+2) here.
    #pragma unroll 1
    for (int k = 0; k < NKIT; k++) {
        if (k + 1 < NKIT) stage_A(k + 1, (k + 1) % 3);
        CP_COMMIT();
        if (k + 2 < NKIT) stage_T(k + 2, (k + 2) % 3);
        CP_COMMIT();
        CP_WAIT2();            // forces A(k), T(k+1) complete
        __syncthreads();       // genB(k) stores visible; lagging readers done

        int a_cur = k % 3;
        int t_nxt = (k + 1) % 3;
        int b_cur = k & 1;
        bool do_gen = (k + 1 < NKIT);

        uint32_t aA = aAddr0 + (uint32_t)(a_cur * ABUF) * 2;
        uint32_t bA = bAddr0 + (uint32_t)(b_cur * BBUF) * 2;

        GenRegs g;
        if (do_gen) gen_load(gc, t_nxt, g);

        #pragma unroll
        for (int ks = 0; ks < 4; ks++) {
            uint32_t af[4][4], bf[4][4];
            #pragma unroll
            for (int im = 0; im < 4; im++)
                ldsm4(af[im], aA + (uint32_t)(im * 16 * ASTRIDE) * 2 + ks * 32);
            #pragma unroll
            for (int in = 0; in < 4; in++)
                ldsm4t(bf[in], bA + (uint32_t)(ks * 16 * BSTRIDE) * 2 + in * 32);
            #pragma unroll
            for (int im = 0; im < 4; im++)
                #pragma unroll
                for (int in = 0; in < 4; in++) {
                    mma16816(acc[im][2 * in],     af[im], &bf[in][0]);
                    mma16816(acc[im][2 * in + 1], af[im], &bf[in][2]);
                }

            // interleave genB(k+1) between ks blocks
            if (ks == 0 && do_gen) {
                gen_store(gc, b_cur ^ 1, g);
                gen_load(gc + 32, t_nxt, g);
            } else if (ks == 2 && do_gen) {
                gen_store(gc + 32, b_cur ^ 1, g);
            }
        }
    }

    // ---- epilogue: direct STG, 32B-sector coalesced -------------------------
    #pragma unroll
    for (int im = 0; im < 4; im++) {
        int o = ot * 256 + m0 + im * 16 + (lane >> 2);
        float* p = out + ((size_t)(b * CHANNELS + o)) * HW
                       + (size_t)pt * 128 + n0 + 2 * (lane & 3);
        #pragma unroll
        for (int inf = 0; inf < 8; inf++) {
            float2 vlo = make_float2(acc[im][inf][0], acc[im][inf][1]);
            float2 vhi = make_float2(acc[im][inf][2], acc[im][inf][3]);
            *(float2*)(p + inf * 8)          = vlo;   // row o
            *(float2*)(p + inf * 8 + 8 * HW) = vhi;   // row o+8
        }
    }
}

// ---------------- launch ------------------------------------------------------
extern "C" void kernel_launch(void* const* d_in, const int* in_sizes, int n_in,
                              void* d_out, int out_size) {
    const float* w        = (const float*)d_in[0];
    const float* affine_w = (const float*)d_in[1];
    const float* affine_b = (const float*)d_in[2];
    const float* freqs    = (const float*)d_in[3];
    const float* phases   = (const float*)d_in[4];
    const float* weight   = (const float*)d_in[5];
    float* out = (float*)d_out;

    cudaFuncSetAttribute(gemm_mma, cudaFuncAttributeMaxDynamicSharedMemorySize,
                         SMEM_BYTES);

    params_kernel<<<1, 128>>>(w, affine_w, affine_b, freqs, phases);
    wconv_kernel<<<512, 256>>>(weight);
    tables_kernel<<<dim3(CHANNELS / 4, BATCH), 256>>>();
    gemm_mma<<<dim3(4, 32, BATCH), 256, SMEM_BYTES>>>(out);
}